// round 15
// baseline (speedup 1.0000x reference)
#include <cuda_runtime.h>
#include <cuda_fp16.h>
#include <math.h>
#include <stdint.h>

// ===========================================================================
// out[M,N] = x[M,K] @ (w * nm_mask(w))[N,K]^T + bias[N]
// M=16384, N=2048, K=2048 fp32.
// fp16 mma.sync (fp32 accum), rel_err ~2.9e-4.
// Overlapped prep: 32 producer CTAs convert w (masked) then 16 x-phases
// (1024 rows each) with line-padded flags; 2048 consumer CTAs gate ONCE
// (nanosleep backoff) then run the R8-proven GEMM
// (CTA 128x128, 256 thr, 8 warps 2x4, 3-stage cp.async, 2 CTAs/SM).
// ===========================================================================

__device__ __half g_xh[16384 * 2048];
__device__ __half g_wh[2048 * 2048];
__device__ int    g_flag[17][32];     // [0..15]=x phases, [16]=w; 128B apart

#define MDIM 16384
#define NDIM 2048
#define KDIM 2048
#define NPREP 32                      // producer CTAs
#define NTILES 2048
#define NTH 256
#define PTH (NPREP * NTH)             // 8192 producer threads

// ---------------- helpers ---------------------------------------------------
__device__ __forceinline__ uint32_t smem_u32(const void* p) {
    uint32_t a;
    asm("{ .reg .u64 t; cvta.to.shared.u64 t, %1; cvt.u32.u64 %0, t; }"
        : "=r"(a) : "l"(p));
    return a;
}
__device__ __forceinline__ void cp16(uint32_t sm, const void* g) {
    asm volatile("cp.async.cg.shared.global [%0], [%1], 16;" :: "r"(sm), "l"(g));
}
#define CP_COMMIT() asm volatile("cp.async.commit_group;" ::: "memory")
#define CP_WAIT1()  asm volatile("cp.async.wait_group 1;"  ::: "memory")
#define CP_WAIT0()  asm volatile("cp.async.wait_group 0;"  ::: "memory")

__device__ __forceinline__ void ldm4(uint32_t r[4], uint32_t addr) {
    asm volatile("ldmatrix.sync.aligned.m8n8.x4.shared.b16 {%0,%1,%2,%3}, [%4];"
                 : "=r"(r[0]), "=r"(r[1]), "=r"(r[2]), "=r"(r[3]) : "r"(addr));
}
__device__ __forceinline__ void mma16816(float c[4], const uint32_t a[4],
                                         const uint32_t b0, const uint32_t b1) {
    asm volatile(
        "mma.sync.aligned.m16n8k16.row.col.f32.f16.f16.f32 "
        "{%0,%1,%2,%3}, {%4,%5,%6,%7}, {%8,%9}, {%0,%1,%2,%3};"
        : "+f"(c[0]), "+f"(c[1]), "+f"(c[2]), "+f"(c[3])
        : "r"(a[0]), "r"(a[1]), "r"(a[2]), "r"(a[3]), "r"(b0), "r"(b1));
}
__device__ __forceinline__ uint32_t f2h2(float a, float b) {
    __half2 h = __float22half2_rn(make_float2(a, b));
    return *reinterpret_cast<uint32_t*>(&h);
}

// ---------------- GEMM config ----------------------------------------------
#define BM 128
#define BN 128
#define BKE 64
#define NSTAGE 3
#define STG_A 0
#define STG_B 16384
#define STAGE_SZ 32768
#define SMEM_TOTAL (NSTAGE * STAGE_SZ)   // 96 KB

// ===========================================================================
// Flag reset (graph-replay safe)
// ===========================================================================
__global__ void zero_flags_kernel() {
    int t = threadIdx.x;
    if (t < 17 * 32) ((int*)g_flag)[t] = 0;
}

// ===========================================================================
// Producer
// ===========================================================================
__device__ __forceinline__ uint2 mask_quad_to_h4(float4 v) {
    float vals[4] = {v.x, v.y, v.z, v.w};
    float a[4] = {fabsf(v.x), fabsf(v.y), fabsf(v.z), fabsf(v.w)};
    int z1 = 0;
    #pragma unroll
    for (int i = 1; i < 4; i++) if (a[i] < a[z1]) z1 = i;
    a[z1] = INFINITY;
    int z2 = 0;
    #pragma unroll
    for (int i = 1; i < 4; i++) if (a[i] < a[z2]) z2 = i;
    vals[z1] = 0.0f;
    vals[z2] = 0.0f;
    uint2 o;
    o.x = f2h2(vals[0], vals[1]);
    o.y = f2h2(vals[2], vals[3]);
    return o;
}

__device__ void producer_body(const float* __restrict__ x,
                              const float* __restrict__ w,
                              int cta, int tid) {
    const int gt = cta * NTH + tid;              // 0..8191

    // ---- w: 2048*2048/8 = 524288 units, 64 per thread ----------------------
    const float4* wq = reinterpret_cast<const float4*>(w);
    #pragma unroll 4
    for (int j = 0; j < 64; j++) {
        int u = gt + j * PTH;
        uint2 a = mask_quad_to_h4(wq[2 * u]);
        uint2 b = mask_quad_to_h4(wq[2 * u + 1]);
        reinterpret_cast<uint4*>(g_wh)[u] = make_uint4(a.x, a.y, b.x, b.y);
    }
    __syncthreads();
    __threadfence();
    if (tid == 0) atomicAdd(&g_flag[16][0], 1);

    // ---- x: 16 phases of 1024 rows = 262144 units, 32 per thread -----------
    const float4* xq = reinterpret_cast<const float4*>(x);
    for (int p = 0; p < 16; p++) {
        const size_t ubase = (size_t)p * 262144;
        #pragma unroll 4
        for (int j = 0; j < 32; j++) {
            size_t u = ubase + gt + (size_t)j * PTH;
            float4 v0 = xq[2 * u], v1 = xq[2 * u + 1];
            reinterpret_cast<uint4*>(g_xh)[u] =
                make_uint4(f2h2(v0.x, v0.y), f2h2(v0.z, v0.w),
                           f2h2(v1.x, v1.y), f2h2(v1.z, v1.w));
        }
        __syncthreads();
        __threadfence();
        if (tid == 0) atomicAdd(&g_flag[p][0], 1);
    }
}

// ===========================================================================
// Consumer GEMM (R8-proven)
// ===========================================================================
__device__ __forceinline__ void load_stage(uint32_t sb, int slot, int chunk,
                                           int bm, int bn, int tid) {
    const int k0 = chunk * BKE;
    const uint32_t st = sb + slot * STAGE_SZ;
    #pragma unroll
    for (int t = tid; t < 1024; t += NTH) {
        int row = t >> 3, c = t & 7;
        uint32_t so = (uint32_t)(row << 7) + ((c ^ (row & 7)) << 4);
        cp16(st + STG_A + so, g_xh + (size_t)(bm * BM + row) * KDIM + k0 + c * 8);
    }
    #pragma unroll
    for (int t = tid; t < 1024; t += NTH) {
        int row = t >> 3, c = t & 7;
        uint32_t so = (uint32_t)(row << 7) + ((c ^ (row & 7)) << 4);
        cp16(st + STG_B + so, g_wh + (size_t)(bn * BN + row) * KDIM + k0 + c * 8);
    }
}

__global__ __launch_bounds__(NTH, 2)
void fused_kernel(const float* __restrict__ x,
                  const float* __restrict__ w,
                  const float* __restrict__ bias,
                  float* __restrict__ C) {
    extern __shared__ char smem[];
    const int tid = threadIdx.x;

    if (blockIdx.x < NPREP) {
        producer_body(x, w, blockIdx.x, tid);
        return;
    }

    const uint32_t sb = smem_u32(smem);
    const int wid = tid >> 5;
    const int lid = tid & 31;
    const int t = blockIdx.x - NPREP;
    const int bn = t & 15;
    const int bm = t >> 4;

    // one-time gate with backoff (flags on separate cache lines)
    if (tid == 0) {
        volatile int* fw = &g_flag[16][0];
        while (*fw < NPREP) __nanosleep(128);
        volatile int* fx = &g_flag[bm >> 3][0];
        while (*fx < NPREP) __nanosleep(128);
    }
    __syncthreads();

    const int wm = wid >> 2;
    const int wn = wid & 3;

    const int a_r  = lid & 15;
    const int a_ch = lid >> 4;
    const int b_r  = (lid & 7) + ((lid >> 4) << 3);
    const int b_ch = (lid >> 3) & 1;

    float acc[4][4][4];
    #pragma unroll
    for (int i = 0; i < 4; i++)
        #pragma unroll
        for (int j = 0; j < 4; j++)
            #pragma unroll
            for (int r = 0; r < 4; r++)
                acc[i][j][r] = 0.0f;

    const int NIT = KDIM / BKE;       // 32
    load_stage(sb, 0, 0, bm, bn, tid); CP_COMMIT();
    load_stage(sb, 1, 1, bm, bn, tid); CP_COMMIT();

    int s = 0, sl = 2;
    for (int i = 0; i < NIT; i++) {
        CP_WAIT1();
        __syncthreads();
        if (i + 2 < NIT) load_stage(sb, sl, i + 2, bm, bn, tid);
        CP_COMMIT();

        const uint32_t A = sb + s * STAGE_SZ + STG_A;
        const uint32_t B = sb + s * STAGE_SZ + STG_B;
        #pragma unroll
        for (int kk = 0; kk < 4; kk++) {
            uint32_t af[4][4], bf[4][2];
            #pragma unroll
            for (int mt = 0; mt < 4; mt++) {
                int row = wm * 64 + mt * 16 + a_r;
                int c = (kk << 1) + a_ch;
                ldm4(af[mt], A + (row << 7) + ((c ^ (row & 7)) << 4));
            }
            #pragma unroll
            for (int bt = 0; bt < 2; bt++) {
                int row = wn * 32 + bt * 16 + b_r;
                int c = (kk << 1) + b_ch;
                uint32_t rb[4];
                ldm4(rb, B + (row << 7) + ((c ^ (row & 7)) << 4));
                bf[2 * bt + 0][0] = rb[0]; bf[2 * bt + 0][1] = rb[1];
                bf[2 * bt + 1][0] = rb[2]; bf[2 * bt + 1][1] = rb[3];
            }
            #pragma unroll
            for (int mt = 0; mt < 4; mt++)
                #pragma unroll
                for (int nt = 0; nt < 4; nt++)
                    mma16816(acc[mt][nt], af[mt], bf[nt][0], bf[nt][1]);
        }
        s  = (s  == NSTAGE - 1) ? 0 : s + 1;
        sl = (sl == NSTAGE - 1) ? 0 : sl + 1;
    }

    // ---------------- epilogue ----------------------------------------------
    CP_WAIT0();
    __syncthreads();
    float* stg = reinterpret_cast<float*>(smem);   // [128][132]
    #pragma unroll
    for (int mt = 0; mt < 4; mt++)
        #pragma unroll
        for (int nt = 0; nt < 4; nt++) {
            int r0 = wm * 64 + mt * 16 + (lid >> 2);
            int col = wn * 32 + nt * 8 + ((lid & 3) << 1);
            *reinterpret_cast<float2*>(&stg[r0 * 132 + col]) =
                make_float2(acc[mt][nt][0], acc[mt][nt][1]);
            *reinterpret_cast<float2*>(&stg[(r0 + 8) * 132 + col]) =
                make_float2(acc[mt][nt][2], acc[mt][nt][3]);
        }
    __syncthreads();
    {
        int c4 = (tid & 31) << 2;
        int r0 = (tid >> 5) << 4;
        float4 b4 = *reinterpret_cast<const float4*>(bias + bn * BN + c4);
        #pragma unroll
        for (int rr = 0; rr < 16; rr++) {
            int row = r0 + rr;
            float4 v = *reinterpret_cast<float4*>(&stg[row * 132 + c4]);
            v.x += b4.x; v.y += b4.y; v.z += b4.z; v.w += b4.w;
            *reinterpret_cast<float4*>(
                C + (size_t)(bm * BM + row) * NDIM + bn * BN + c4) = v;
        }
    }
}

// ===========================================================================
// Launch
// ===========================================================================
extern "C" void kernel_launch(void* const* d_in, const int* in_sizes, int n_in,
                              void* d_out, int out_size) {
    const float* x    = (const float*)d_in[0];  // [M,K]
    const float* w    = (const float*)d_in[1];  // [N,K]
    const float* bias = (const float*)d_in[2];  // [N]
    float* out = (float*)d_out;                 // [M,N]

    zero_flags_kernel<<<1, 544>>>();

    cudaFuncSetAttribute(fused_kernel,
                         cudaFuncAttributeMaxDynamicSharedMemorySize, SMEM_TOTAL);
    fused_kernel<<<NPREP + NTILES, NTH, SMEM_TOTAL>>>(x, w, bias, out);
}

// round 16
// speedup vs baseline: 1.1294x; 1.1294x over previous
#include <cuda_runtime.h>
#include <cuda_fp16.h>
#include <math.h>
#include <stdint.h>

// ===========================================================================
// out[M,N] = x[M,K] @ (w * nm_mask(w))[N,K]^T + bias[N]
// M=16384, N=2048, K=2048 fp32.
// fp16 mma.sync (fp32 accum), rel_err ~2.9e-4.
// Self-serve conversion: each GEMM CTA converts its own 8-row x slice
// (group [t&~15, t|15] covers its bm band); blocks 0..295 (wave-1) share
// w conversion. One gated wait, then the R8-proven GEMM
// (CTA 128x128, 256 thr, 8 warps 2x4, 3-stage cp.async, 2 CTAs/SM).
// ===========================================================================

__device__ __half g_xh[16384 * 2048];
__device__ __half g_wh[2048 * 2048];
__device__ int    g_fw[32];            // w flag (own 128B line)
__device__ int    g_fx[128][32];       // x group flags (own lines)

#define MDIM 16384
#define NDIM 2048
#define KDIM 2048
#define NTILES 2048
#define NTH 256
#define W_CTAS 296                     // wave-1 resident blocks do w

// ---------------- helpers ---------------------------------------------------
__device__ __forceinline__ uint32_t smem_u32(const void* p) {
    uint32_t a;
    asm("{ .reg .u64 t; cvta.to.shared.u64 t, %1; cvt.u32.u64 %0, t; }"
        : "=r"(a) : "l"(p));
    return a;
}
__device__ __forceinline__ void cp16(uint32_t sm, const void* g) {
    asm volatile("cp.async.cg.shared.global [%0], [%1], 16;" :: "r"(sm), "l"(g));
}
#define CP_COMMIT() asm volatile("cp.async.commit_group;" ::: "memory")
#define CP_WAIT1()  asm volatile("cp.async.wait_group 1;"  ::: "memory")
#define CP_WAIT0()  asm volatile("cp.async.wait_group 0;"  ::: "memory")

__device__ __forceinline__ void ldm4(uint32_t r[4], uint32_t addr) {
    asm volatile("ldmatrix.sync.aligned.m8n8.x4.shared.b16 {%0,%1,%2,%3}, [%4];"
                 : "=r"(r[0]), "=r"(r[1]), "=r"(r[2]), "=r"(r[3]) : "r"(addr));
}
__device__ __forceinline__ void mma16816(float c[4], const uint32_t a[4],
                                         const uint32_t b0, const uint32_t b1) {
    asm volatile(
        "mma.sync.aligned.m16n8k16.row.col.f32.f16.f16.f32 "
        "{%0,%1,%2,%3}, {%4,%5,%6,%7}, {%8,%9}, {%0,%1,%2,%3};"
        : "+f"(c[0]), "+f"(c[1]), "+f"(c[2]), "+f"(c[3])
        : "r"(a[0]), "r"(a[1]), "r"(a[2]), "r"(a[3]), "r"(b0), "r"(b1));
}
__device__ __forceinline__ uint32_t f2h2(float a, float b) {
    __half2 h = __float22half2_rn(make_float2(a, b));
    return *reinterpret_cast<uint32_t*>(&h);
}

// ---------------- GEMM config ----------------------------------------------
#define BM 128
#define BN 128
#define BKE 64
#define NSTAGE 3
#define STG_A 0
#define STG_B 16384
#define STAGE_SZ 32768
#define SMEM_TOTAL (NSTAGE * STAGE_SZ)   // 96 KB

// ===========================================================================
// Flag reset (graph-replay safe)
// ===========================================================================
__global__ void zero_flags_kernel() {
    int t = blockIdx.x * blockDim.x + threadIdx.x;
    if (t < 32) g_fw[t] = 0;
    if (t < 128 * 32) ((int*)g_fx)[t] = 0;
}

// ===========================================================================
// Conversion helpers
// ===========================================================================
__device__ __forceinline__ uint2 mask_quad_to_h4(float4 v) {
    float vals[4] = {v.x, v.y, v.z, v.w};
    float a[4] = {fabsf(v.x), fabsf(v.y), fabsf(v.z), fabsf(v.w)};
    int z1 = 0;
    #pragma unroll
    for (int i = 1; i < 4; i++) if (a[i] < a[z1]) z1 = i;
    a[z1] = INFINITY;
    int z2 = 0;
    #pragma unroll
    for (int i = 1; i < 4; i++) if (a[i] < a[z2]) z2 = i;
    vals[z1] = 0.0f;
    vals[z2] = 0.0f;
    uint2 o;
    o.x = f2h2(vals[0], vals[1]);
    o.y = f2h2(vals[2], vals[3]);
    return o;
}

// ===========================================================================
// Fused kernel: grid = 2048 consumer CTAs (no dedicated producers)
// ===========================================================================
__global__ __launch_bounds__(NTH, 2)
void fused_kernel(const float* __restrict__ x,
                  const float* __restrict__ w,
                  const float* __restrict__ bias,
                  float* __restrict__ C) {
    extern __shared__ char smem[];
    const uint32_t sb = smem_u32(smem);
    const int tid = threadIdx.x;
    const int t = blockIdx.x;
    const int bn = t & 15;
    const int bm = t >> 4;
    const int grp = t >> 4;            // x group == bm

    // ---- phase 1: convert own x slice: rows [8t, 8t+8), 2048 units of 8 ----
    {
        const float4* xq = reinterpret_cast<const float4*>(x);
        const size_t u0 = (size_t)t * 2048;
        #pragma unroll
        for (int j = 0; j < 8; j++) {
            size_t u = u0 + tid + j * NTH;
            float4 v0 = xq[2 * u], v1 = xq[2 * u + 1];
            reinterpret_cast<uint4*>(g_xh)[u] =
                make_uint4(f2h2(v0.x, v0.y), f2h2(v0.z, v0.w),
                           f2h2(v1.x, v1.y), f2h2(v1.z, v1.w));
        }
        __threadfence();
        __syncthreads();
        if (tid == 0) atomicAdd(&g_fx[grp][0], 1);
    }

    // ---- phase 2: blocks [0, 296) share w conversion -----------------------
    if (t < W_CTAS) {
        const float4* wq = reinterpret_cast<const float4*>(w);
        const int NWU = NDIM * KDIM / 8;            // 524288 units
        const int stride = W_CTAS * NTH;            // 75776
        for (int u = t * NTH + tid; u < NWU; u += stride) {
            uint2 a = mask_quad_to_h4(wq[2 * u]);
            uint2 b = mask_quad_to_h4(wq[2 * u + 1]);
            reinterpret_cast<uint4*>(g_wh)[u] = make_uint4(a.x, a.y, b.x, b.y);
        }
        __threadfence();
        __syncthreads();
        if (tid == 0) atomicAdd(&g_fw[0], 1);
    }

    // ---- gate: need all w + own x group (16 members) -----------------------
    if (tid == 0) {
        volatile int* fw = &g_fw[0];
        while (*fw < W_CTAS) __nanosleep(64);
        volatile int* fx = &g_fx[grp][0];
        while (*fx < 16) __nanosleep(64);
    }
    __syncthreads();

    // ---- R8-proven GEMM ----------------------------------------------------
    const int wid = tid >> 5;
    const int lid = tid & 31;
    const int wm = wid >> 2;
    const int wn = wid & 3;

    const int a_r  = lid & 15;
    const int a_ch = lid >> 4;
    const int b_r  = (lid & 7) + ((lid >> 4) << 3);
    const int b_ch = (lid >> 3) & 1;

    float acc[4][4][4];
    #pragma unroll
    for (int i = 0; i < 4; i++)
        #pragma unroll
        for (int j = 0; j < 4; j++)
            #pragma unroll
            for (int r = 0; r < 4; r++)
                acc[i][j][r] = 0.0f;

    const int NIT = KDIM / BKE;       // 32

    // loader lambda-ish (macro-free, inlined twice via helper)
    #define LOAD_STAGE(slot, chunk) do {                                        \
        const int k0 = (chunk) * BKE;                                           \
        const uint32_t st = sb + (slot) * STAGE_SZ;                             \
        _Pragma("unroll")                                                       \
        for (int tt = tid; tt < 1024; tt += NTH) {                              \
            int row = tt >> 3, c = tt & 7;                                      \
            uint32_t so = (uint32_t)(row << 7) + ((c ^ (row & 7)) << 4);        \
            cp16(st + STG_A + so,                                               \
                 g_xh + (size_t)(bm * BM + row) * KDIM + k0 + c * 8);           \
        }                                                                       \
        _Pragma("unroll")                                                       \
        for (int tt = tid; tt < 1024; tt += NTH) {                              \
            int row = tt >> 3, c = tt & 7;                                      \
            uint32_t so = (uint32_t)(row << 7) + ((c ^ (row & 7)) << 4);        \
            cp16(st + STG_B + so,                                               \
                 g_wh + (size_t)(bn * BN + row) * KDIM + k0 + c * 8);           \
        }                                                                       \
    } while (0)

    LOAD_STAGE(0, 0); CP_COMMIT();
    LOAD_STAGE(1, 1); CP_COMMIT();

    int s = 0, sl = 2;
    for (int i = 0; i < NIT; i++) {
        CP_WAIT1();
        __syncthreads();
        if (i + 2 < NIT) LOAD_STAGE(sl, i + 2);
        CP_COMMIT();

        const uint32_t A = sb + s * STAGE_SZ + STG_A;
        const uint32_t B = sb + s * STAGE_SZ + STG_B;
        #pragma unroll
        for (int kk = 0; kk < 4; kk++) {
            uint32_t af[4][4], bf[4][2];
            #pragma unroll
            for (int mt = 0; mt < 4; mt++) {
                int row = wm * 64 + mt * 16 + a_r;
                int c = (kk << 1) + a_ch;
                ldm4(af[mt], A + (row << 7) + ((c ^ (row & 7)) << 4));
            }
            #pragma unroll
            for (int bt = 0; bt < 2; bt++) {
                int row = wn * 32 + bt * 16 + b_r;
                int c = (kk << 1) + b_ch;
                uint32_t rb[4];
                ldm4(rb, B + (row << 7) + ((c ^ (row & 7)) << 4));
                bf[2 * bt + 0][0] = rb[0]; bf[2 * bt + 0][1] = rb[1];
                bf[2 * bt + 1][0] = rb[2]; bf[2 * bt + 1][1] = rb[3];
            }
            #pragma unroll
            for (int mt = 0; mt < 4; mt++)
                #pragma unroll
                for (int nt = 0; nt < 4; nt++)
                    mma16816(acc[mt][nt], af[mt], bf[nt][0], bf[nt][1]);
        }
        s  = (s  == NSTAGE - 1) ? 0 : s + 1;
        sl = (sl == NSTAGE - 1) ? 0 : sl + 1;
    }

    // ---------------- epilogue ----------------------------------------------
    CP_WAIT0();
    __syncthreads();
    float* stg = reinterpret_cast<float*>(smem);   // [128][132]
    #pragma unroll
    for (int mt = 0; mt < 4; mt++)
        #pragma unroll
        for (int nt = 0; nt < 4; nt++) {
            int r0 = wm * 64 + mt * 16 + (lid >> 2);
            int col = wn * 32 + nt * 8 + ((lid & 3) << 1);
            *reinterpret_cast<float2*>(&stg[r0 * 132 + col]) =
                make_float2(acc[mt][nt][0], acc[mt][nt][1]);
            *reinterpret_cast<float2*>(&stg[(r0 + 8) * 132 + col]) =
                make_float2(acc[mt][nt][2], acc[mt][nt][3]);
        }
    __syncthreads();
    {
        int c4 = (tid & 31) << 2;
        int r0 = (tid >> 5) << 4;
        float4 b4 = *reinterpret_cast<const float4*>(bias + bn * BN + c4);
        #pragma unroll
        for (int rr = 0; rr < 16; rr++) {
            int row = r0 + rr;
            float4 v = *reinterpret_cast<float4*>(&stg[row * 132 + c4]);
            v.x += b4.x; v.y += b4.y; v.z += b4.z; v.w += b4.w;
            *reinterpret_cast<float4*>(
                C + (size_t)(bm * BM + row) * NDIM + bn * BN + c4) = v;
        }
    }
}

// ===========================================================================
// Launch
// ===========================================================================
extern "C" void kernel_launch(void* const* d_in, const int* in_sizes, int n_in,
                              void* d_out, int out_size) {
    const float* x    = (const float*)d_in[0];  // [M,K]
    const float* w    = (const float*)d_in[1];  // [N,K]
    const float* bias = (const float*)d_in[2];  // [N]
    float* out = (float*)d_out;                 // [M,N]

    zero_flags_kernel<<<17, 256>>>();

    cudaFuncSetAttribute(fused_kernel,
                         cudaFuncAttributeMaxDynamicSharedMemorySize, SMEM_TOTAL);
    fused_kernel<<<NTILES, NTH, SMEM_TOTAL>>>(x, w, bias, out);
}

// round 17
// speedup vs baseline: 1.2185x; 1.0789x over previous
#include <cuda_runtime.h>
#include <cuda_fp16.h>
#include <math.h>
#include <stdint.h>

// ===========================================================================
// out[M,N] = x[M,K] @ (w * nm_mask(w))[N,K]^T + bias[N]
// M=16384, N=2048, K=2048 fp32.
// Single-pass fp16 mma.sync (fp32 accum), rel_err ~2.9e-4.
// CTA 128x128, 256 threads (8 warps 2x4, warp tile 64x32),
// 3-stage cp.async ring, 2 CTAs/SM.  (R8 configuration — measured floor:
// GEMM issue-saturated at tensor=71.9%, prep at DRAM BW floor.)
// ===========================================================================

__device__ __half g_xh[16384 * 2048];
__device__ __half g_wh[2048 * 2048];

// ---------------- helpers ---------------------------------------------------
__device__ __forceinline__ uint32_t smem_u32(const void* p) {
    uint32_t a;
    asm("{ .reg .u64 t; cvta.to.shared.u64 t, %1; cvt.u32.u64 %0, t; }"
        : "=r"(a) : "l"(p));
    return a;
}
__device__ __forceinline__ void cp16(uint32_t sm, const void* g) {
    asm volatile("cp.async.cg.shared.global [%0], [%1], 16;" :: "r"(sm), "l"(g));
}
#define CP_COMMIT() asm volatile("cp.async.commit_group;" ::: "memory")
#define CP_WAIT1()  asm volatile("cp.async.wait_group 1;"  ::: "memory")
#define CP_WAIT0()  asm volatile("cp.async.wait_group 0;"  ::: "memory")

__device__ __forceinline__ void ldm4(uint32_t r[4], uint32_t addr) {
    asm volatile("ldmatrix.sync.aligned.m8n8.x4.shared.b16 {%0,%1,%2,%3}, [%4];"
                 : "=r"(r[0]), "=r"(r[1]), "=r"(r[2]), "=r"(r[3]) : "r"(addr));
}
__device__ __forceinline__ void mma16816(float c[4], const uint32_t a[4],
                                         const uint32_t b0, const uint32_t b1) {
    asm volatile(
        "mma.sync.aligned.m16n8k16.row.col.f32.f16.f16.f32 "
        "{%0,%1,%2,%3}, {%4,%5,%6,%7}, {%8,%9}, {%0,%1,%2,%3};"
        : "+f"(c[0]), "+f"(c[1]), "+f"(c[2]), "+f"(c[3])
        : "r"(a[0]), "r"(a[1]), "r"(a[2]), "r"(a[3]), "r"(b0), "r"(b1));
}

// ---------------- GEMM config ----------------------------------------------
#define BM 128
#define BN 128
#define BKE 64               // fp16 elems per k-chunk = 128 B/row
#define NTH 256
#define NSTAGE 3
#define STG_A 0              // 16 KB (128 rows x 128 B)
#define STG_B 16384          // 16 KB
#define STAGE_SZ 32768
#define SMEM_TOTAL (NSTAGE * STAGE_SZ)   // 96 KB

// ===========================================================================
// Fused prep: blocks [0, wb) -> weight mask+convert; rest -> x convert.
// Each thread: 8 floats (2 float4 loads -> 1 uint4 store).
// ===========================================================================
__device__ __forceinline__ uint2 mask_quad_to_h4(float4 v) {
    float vals[4] = {v.x, v.y, v.z, v.w};
    float a[4] = {fabsf(v.x), fabsf(v.y), fabsf(v.z), fabsf(v.w)};
    int z1 = 0;
    #pragma unroll
    for (int i = 1; i < 4; i++) if (a[i] < a[z1]) z1 = i;
    a[z1] = INFINITY;
    int z2 = 0;
    #pragma unroll
    for (int i = 1; i < 4; i++) if (a[i] < a[z2]) z2 = i;
    vals[z1] = 0.0f;
    vals[z2] = 0.0f;
    __half2 h01(__float2half(vals[0]), __float2half(vals[1]));
    __half2 h23(__float2half(vals[2]), __float2half(vals[3]));
    uint2 o;
    o.x = *reinterpret_cast<uint32_t*>(&h01);
    o.y = *reinterpret_cast<uint32_t*>(&h23);
    return o;
}
__device__ __forceinline__ uint2 quad_to_h4(float4 v) {
    __half2 h01(__float2half(v.x), __float2half(v.y));
    __half2 h23(__float2half(v.z), __float2half(v.w));
    uint2 o;
    o.x = *reinterpret_cast<uint32_t*>(&h01);
    o.y = *reinterpret_cast<uint32_t*>(&h23);
    return o;
}

__global__ void prep_fused_kernel(const float* __restrict__ w,
                                  const float* __restrict__ x,
                                  int wb, int n_wu, int n_xu) {
    if (blockIdx.x < (unsigned)wb) {
        int u = blockIdx.x * blockDim.x + threadIdx.x;
        if (u >= n_wu) return;
        const float4* wq = reinterpret_cast<const float4*>(w);
        float4 v0 = wq[u * 2 + 0];
        float4 v1 = wq[u * 2 + 1];
        uint2 a = mask_quad_to_h4(v0);
        uint2 b = mask_quad_to_h4(v1);
        reinterpret_cast<uint4*>(g_wh)[u] = make_uint4(a.x, a.y, b.x, b.y);
    } else {
        int u = (blockIdx.x - wb) * blockDim.x + threadIdx.x;
        if (u >= n_xu) return;
        const float4* xq = reinterpret_cast<const float4*>(x);
        float4 v0 = xq[u * 2 + 0];
        float4 v1 = xq[u * 2 + 1];
        uint2 a = quad_to_h4(v0);
        uint2 b = quad_to_h4(v1);
        reinterpret_cast<uint4*>(g_xh)[u] = make_uint4(a.x, a.y, b.x, b.y);
    }
}

// ===========================================================================
// GEMM. grid=(N/128 fast, M/128), 256 threads (8 warps 2x4), warp tile 64x32.
// ===========================================================================
__device__ __forceinline__ void load_stage(uint32_t sb, int slot, int chunk,
                                           int bm, int bn, int tid, int K) {
    const int k0 = chunk * BKE;
    const uint32_t st = sb + slot * STAGE_SZ;
    #pragma unroll
    for (int t = tid; t < 1024; t += NTH) {       // A: 128 rows x 8 chunks
        int row = t >> 3, c = t & 7;
        uint32_t so = (uint32_t)(row << 7) + ((c ^ (row & 7)) << 4);
        cp16(st + STG_A + so, g_xh + (size_t)(bm * BM + row) * K + k0 + c * 8);
    }
    #pragma unroll
    for (int t = tid; t < 1024; t += NTH) {       // B: 128 rows x 8 chunks
        int row = t >> 3, c = t & 7;
        uint32_t so = (uint32_t)(row << 7) + ((c ^ (row & 7)) << 4);
        cp16(st + STG_B + so, g_wh + (size_t)(bn * BN + row) * K + k0 + c * 8);
    }
}

__global__ __launch_bounds__(NTH, 2)
void gemm_mma_kernel(const float* __restrict__ bias,
                     float* __restrict__ C,
                     int M, int N, int K) {
    extern __shared__ char smem[];
    const uint32_t sb = smem_u32(smem);
    const int tid = threadIdx.x;
    const int wid = tid >> 5;
    const int lid = tid & 31;
    const int bn = blockIdx.x;
    const int bm = blockIdx.y;

    const int wm = wid >> 2;          // 0..1 -> 64-row A band
    const int wn = wid & 3;           // 0..3 -> 32-row B band

    const int a_r  = lid & 15;
    const int a_ch = lid >> 4;
    const int b_r  = (lid & 7) + ((lid >> 4) << 3);
    const int b_ch = (lid >> 3) & 1;

    float acc[4][4][4];
    #pragma unroll
    for (int i = 0; i < 4; i++)
        #pragma unroll
        for (int j = 0; j < 4; j++)
            #pragma unroll
            for (int r = 0; r < 4; r++)
                acc[i][j][r] = 0.0f;

    const int NIT = K / BKE;          // 32
    load_stage(sb, 0, 0, bm, bn, tid, K); CP_COMMIT();
    load_stage(sb, 1, 1, bm, bn, tid, K); CP_COMMIT();

    int s = 0, sl = 2;
    for (int i = 0; i < NIT; i++) {
        CP_WAIT1();
        __syncthreads();
        if (i + 2 < NIT) load_stage(sb, sl, i + 2, bm, bn, tid, K);
        CP_COMMIT();

        const uint32_t A = sb + s * STAGE_SZ + STG_A;
        const uint32_t B = sb + s * STAGE_SZ + STG_B;
        #pragma unroll
        for (int kk = 0; kk < 4; kk++) {
            uint32_t af[4][4], bf[4][2];
            #pragma unroll
            for (int mt = 0; mt < 4; mt++) {
                int row = wm * 64 + mt * 16 + a_r;
                int c = (kk << 1) + a_ch;
                ldm4(af[mt], A + (row << 7) + ((c ^ (row & 7)) << 4));
            }
            #pragma unroll
            for (int bt = 0; bt < 2; bt++) {
                int row = wn * 32 + bt * 16 + b_r;
                int c = (kk << 1) + b_ch;
                uint32_t rb[4];
                ldm4(rb, B + (row << 7) + ((c ^ (row & 7)) << 4));
                bf[2 * bt + 0][0] = rb[0]; bf[2 * bt + 0][1] = rb[1];
                bf[2 * bt + 1][0] = rb[2]; bf[2 * bt + 1][1] = rb[3];
            }
            #pragma unroll
            for (int mt = 0; mt < 4; mt++)
                #pragma unroll
                for (int nt = 0; nt < 4; nt++)
                    mma16816(acc[mt][nt], af[mt], bf[nt][0], bf[nt][1]);
        }
        s  = (s  == NSTAGE - 1) ? 0 : s + 1;
        sl = (sl == NSTAGE - 1) ? 0 : sl + 1;
    }

    // ---------------- epilogue ----------------------------------------------
    CP_WAIT0();
    __syncthreads();
    float* stg = reinterpret_cast<float*>(smem);   // [128][132]
    #pragma unroll
    for (int mt = 0; mt < 4; mt++)
        #pragma unroll
        for (int nt = 0; nt < 4; nt++) {
            int r0 = wm * 64 + mt * 16 + (lid >> 2);
            int col = wn * 32 + nt * 8 + ((lid & 3) << 1);
            *reinterpret_cast<float2*>(&stg[r0 * 132 + col]) =
                make_float2(acc[mt][nt][0], acc[mt][nt][1]);
            *reinterpret_cast<float2*>(&stg[(r0 + 8) * 132 + col]) =
                make_float2(acc[mt][nt][2], acc[mt][nt][3]);
        }
    __syncthreads();
    {
        // each thread: 16 rows of one 4-col group; bias loaded once
        int c4 = (tid & 31) << 2;
        int r0 = (tid >> 5) << 4;
        float4 b4 = *reinterpret_cast<const float4*>(bias + bn * BN + c4);
        #pragma unroll
        for (int rr = 0; rr < 16; rr++) {
            int row = r0 + rr;
            float4 v = *reinterpret_cast<float4*>(&stg[row * 132 + c4]);
            v.x += b4.x; v.y += b4.y; v.z += b4.z; v.w += b4.w;
            *reinterpret_cast<float4*>(
                C + (size_t)(bm * BM + row) * N + bn * BN + c4) = v;
        }
    }
}

// ===========================================================================
// Launch
// ===========================================================================
extern "C" void kernel_launch(void* const* d_in, const int* in_sizes, int n_in,
                              void* d_out, int out_size) {
    const float* x    = (const float*)d_in[0];  // [M,K]
    const float* w    = (const float*)d_in[1];  // [N,K]
    const float* bias = (const float*)d_in[2];  // [N]
    float* out = (float*)d_out;                 // [M,N]

    const int O = in_sizes[2];          // 2048
    const int H = in_sizes[1] / O;      // 2048
    const int M = in_sizes[0] / H;      // 16384

    const int n_wu = O * H / 8;
    const int n_xu = M * H / 8;
    const int wb = (n_wu + 255) / 256;
    const int xb = (n_xu + 255) / 256;
    prep_fused_kernel<<<wb + xb, 256>>>(w, x, wb, n_wu, n_xu);

    cudaFuncSetAttribute(gemm_mma_kernel,
                         cudaFuncAttributeMaxDynamicSharedMemorySize, SMEM_TOTAL);
    dim3 grid(O / BN, M / BM);          // (16, 128), N fastest
    gemm_mma_kernel<<<grid, NTH, SMEM_TOTAL>>>(bias, out, M, O, H);
}